// round 2
// baseline (speedup 1.0000x reference)
#include <cuda_runtime.h>
#include <cuda_bf16.h>
#include <math.h>

// ---------------------------------------------------------------------------
// EEGformer forward, fp32 SIMT implementation.
// Shapes: A=120, B=2048, Bp1=2049, M=128, T = 120*2049 = 245880 tokens.
// ---------------------------------------------------------------------------

#define AA    120
#define BB    2048
#define BP1   2049
#define MM    128
#define TTOK  (AA * BP1)      // 245880
#define TXTOK (AA * BB)       // 245760

// Scratch (device globals; no dynamic allocation allowed).
// g_z doubles as the imv buffer (z is dead after the QKV GEMM reads it).
__device__ float g_z  [(size_t)TTOK * 128];   // LN output / imv    (~126 MB)
__device__ float g_big[(size_t)TTOK * 512];   // qkv (384) / mlp h  (~504 MB)

// ---------------------------------------------------------------------------
// Generic SGEMM: C[orow, n] = sum_k A[t, k] * W[n, k]  (+bias[n]) (gelu?) (+addend[orow,n])
//   BM=BN=128, BK=16, 256 threads, 8x8 per-thread tile (split 4+4).
//   REMAP: orow = t + t/2048 + 1 (init projection writes rows 1..2048 of each i).
// ---------------------------------------------------------------------------
template<int REMAP, int GELU_F>
__global__ __launch_bounds__(256)
void gemm_kernel(const float* __restrict__ A, int lda,
                 const float* __restrict__ W,
                 const float* __restrict__ biasv,     // [N] or null
                 const float* __restrict__ addend,    // [rows, N] or null
                 float* __restrict__ C,               // [rows, N]
                 int T, int N, int K)
{
    __shared__ float As[128 * 17];
    __shared__ float Bs[128 * 17];

    const int tid = threadIdx.x;
    const int tx  = tid & 15;         // 0..15  -> output cols
    const int ty  = tid >> 4;         // 0..15  -> output rows
    const int t0  = blockIdx.x * 128;
    const int n0  = blockIdx.y * 128;

    float acc[8][8];
#pragma unroll
    for (int i = 0; i < 8; i++)
#pragma unroll
        for (int j = 0; j < 8; j++) acc[i][j] = 0.0f;

    for (int k0 = 0; k0 < K; k0 += 16) {
        // Load A tile (128 rows x 16 k) and W tile (128 n x 16 k), padded stride 17.
#pragma unroll
        for (int it = 0; it < 2; it++) {
            int l   = tid + it * 256;          // 0..511
            int row = l >> 2;
            int kq  = (l & 3) * 4;
            int t   = t0 + row;
            float4 va = make_float4(0.f, 0.f, 0.f, 0.f);
            if (t < T) va = *(const float4*)(A + (size_t)t * lda + k0 + kq);
            As[row * 17 + kq + 0] = va.x;
            As[row * 17 + kq + 1] = va.y;
            As[row * 17 + kq + 2] = va.z;
            As[row * 17 + kq + 3] = va.w;
            int n = n0 + row;
            float4 vb = make_float4(0.f, 0.f, 0.f, 0.f);
            if (n < N) vb = *(const float4*)(W + (size_t)n * K + k0 + kq);
            Bs[row * 17 + kq + 0] = vb.x;
            Bs[row * 17 + kq + 1] = vb.y;
            Bs[row * 17 + kq + 2] = vb.z;
            Bs[row * 17 + kq + 3] = vb.w;
        }
        __syncthreads();

#pragma unroll
        for (int k = 0; k < 16; k++) {
            float a[8], b[8];
#pragma unroll
            for (int m = 0; m < 4; m++) {
                a[m]     = As[(ty * 4 + m) * 17 + k];
                a[4 + m] = As[(64 + ty * 4 + m) * 17 + k];
                b[m]     = Bs[(tx * 4 + m) * 17 + k];
                b[4 + m] = Bs[(64 + tx * 4 + m) * 17 + k];
            }
#pragma unroll
            for (int i = 0; i < 8; i++)
#pragma unroll
                for (int j = 0; j < 8; j++)
                    acc[i][j] = fmaf(a[i], b[j], acc[i][j]);
        }
        __syncthreads();
    }

    // Epilogue
#pragma unroll
    for (int mi = 0; mi < 8; mi++) {
        int row = (mi < 4) ? (ty * 4 + mi) : (64 + ty * 4 + (mi - 4));
        int t = t0 + row;
        if (t >= T) continue;
        size_t orow = REMAP ? ((size_t)t + (size_t)(t / 2048) + 1) : (size_t)t;
        const float* addp = addend ? addend + orow * (size_t)N : nullptr;
        float*       outp = C + orow * (size_t)N;
#pragma unroll
        for (int ni = 0; ni < 8; ni++) {
            int col = (ni < 4) ? (tx * 4 + ni) : (64 + tx * 4 + (ni - 4));
            int n = n0 + col;
            float val = acc[mi][ni];
            if (biasv)  val += biasv[n];
            if (GELU_F) val = 0.5f * val * (1.0f + erff(val * 0.70710678118654752f));
            if (addp)   val += addp[n];
            outp[n] = val;
        }
    }
}

// ---------------------------------------------------------------------------
// LayerNorm over last dim (128). One warp per token, float4 per lane.
// ---------------------------------------------------------------------------
__global__ void ln_kernel(const float* __restrict__ x,
                          const float* __restrict__ g,
                          const float* __restrict__ b,
                          float* __restrict__ z, int T)
{
    int warp = threadIdx.x >> 5;
    int lane = threadIdx.x & 31;
    int t = blockIdx.x * 8 + warp;
    if (t >= T) return;

    float4 v = ((const float4*)(x + (size_t)t * 128))[lane];
    float s = v.x + v.y + v.z + v.w;
#pragma unroll
    for (int o = 16; o >= 1; o >>= 1) s += __shfl_xor_sync(0xffffffffu, s, o);
    float mu = s * (1.0f / 128.0f);
    float dx = v.x - mu, dy = v.y - mu, dz = v.z - mu, dw = v.w - mu;
    float q = dx * dx + dy * dy + dz * dz + dw * dw;
#pragma unroll
    for (int o = 16; o >= 1; o >>= 1) q += __shfl_xor_sync(0xffffffffu, q, o);
    float rs = rsqrtf(q * (1.0f / 128.0f) + 1e-5f);

    float4 gg = ((const float4*)g)[lane];
    float4 bb = ((const float4*)b)[lane];
    float4 o4;
    o4.x = dx * rs * gg.x + bb.x;
    o4.y = dy * rs * gg.y + bb.y;
    o4.z = dz * rs * gg.z + bb.z;
    o4.w = dw * rs * gg.w + bb.w;
    ((float4*)(z + (size_t)t * 128))[lane] = o4;
}

// ---------------------------------------------------------------------------
// rsa/imv: from qkv (ld 384, layout [q(128) k(128) v(128)], n = h*16+d)
//   rsa[h] = (1/sqrt(16)) * dot(q_h, k_h);  imv[h*16+d] = rsa[h] * v[h*16+d]
// One warp per token; lane covers dims lane*4..lane*4+3 (head = lane/4).
// ---------------------------------------------------------------------------
__global__ void rsa_imv_kernel(const float* __restrict__ qkv,
                               float* __restrict__ imv, int T)
{
    int warp = threadIdx.x >> 5;
    int lane = threadIdx.x & 31;
    int t = blockIdx.x * 8 + warp;
    if (t >= T) return;
    const float* bp = qkv + (size_t)t * 384;
    float4 q = *(const float4*)(bp + lane * 4);
    float4 k = *(const float4*)(bp + 128 + lane * 4);
    float4 v = *(const float4*)(bp + 256 + lane * 4);
    float p = q.x * k.x + q.y * k.y + q.z * k.z + q.w * k.w;
    p += __shfl_xor_sync(0xffffffffu, p, 1);
    p += __shfl_xor_sync(0xffffffffu, p, 2);
    float rsa = p * 0.25f;   // 1/sqrt(16)
    float4 o = make_float4(rsa * v.x, rsa * v.y, rsa * v.z, rsa * v.w);
    *(float4*)(imv + (size_t)t * 128 + lane * 4) = o;
}

// ---------------------------------------------------------------------------
// Sequential cumsum over j in [0, 2048) per (i, feature); row 2048 untouched.
// ---------------------------------------------------------------------------
__global__ void cumsum_kernel(float* __restrict__ imv)
{
    int i = blockIdx.x;
    int f = threadIdx.x;
    size_t base = (size_t)i * BP1 * 128 + f;
    float acc = 0.0f;
    for (int j = 0; j < BB; j += 8) {
        float v[8];
#pragma unroll
        for (int u = 0; u < 8; u++) v[u] = imv[base + (size_t)(j + u) * 128];
#pragma unroll
        for (int u = 0; u < 8; u++) {
            acc += v[u];
            imv[base + (size_t)(j + u) * 128] = acc;
        }
    }
}

// ---------------------------------------------------------------------------
// cls row: s[i,0,:] = cls[i,:] + bias[i,0,:]
// ---------------------------------------------------------------------------
__global__ void cls_kernel(const float* __restrict__ cls,
                           const float* __restrict__ bias,
                           float* __restrict__ out)
{
    int i = blockIdx.x, l = threadIdx.x;
    out[(size_t)i * BP1 * 128 + l] = cls[i * 128 + l] + bias[(size_t)i * BP1 * 128 + l];
}

// ---------------------------------------------------------------------------
// Launch
// ---------------------------------------------------------------------------
extern "C" void kernel_launch(void* const* d_in, const int* in_sizes, int n_in,
                              void* d_out, int out_size)
{
    const float* x      = (const float*)d_in[0];
    const float* weight = (const float*)d_in[1];
    const float* cls    = (const float*)d_in[2];
    const float* bias   = (const float*)d_in[3];
    const float* Wqkv   = (const float*)d_in[4];
    const float* Wo     = (const float*)d_in[5];
    const float* ln1_g  = (const float*)d_in[6];
    const float* ln1_b  = (const float*)d_in[7];
    const float* ln2_g  = (const float*)d_in[8];
    const float* ln2_b  = (const float*)d_in[9];
    const float* fc1_w  = (const float*)d_in[10];
    const float* fc1_b  = (const float*)d_in[11];
    const float* fc2_w  = (const float*)d_in[12];
    const float* fc2_b  = (const float*)d_in[13];
    float* s = (float*)d_out;

    void *pz, *pbig;
    cudaGetSymbolAddress(&pz,   g_z);
    cudaGetSymbolAddress(&pbig, g_big);
    float* z_buf   = (float*)pz;
    float* imv_buf = (float*)pz;     // alias: z dead after QKV GEMM
    float* big_buf = (float*)pbig;

    const int T  = TTOK;
    const int Tx = TXTOK;
    const int tokBlocks = (T + 127) / 128;

    // s = concat([cls, x @ W^T], 1) + bias
    cls_kernel<<<AA, 128>>>(cls, bias, s);
    gemm_kernel<1, 0><<<dim3((Tx + 127) / 128, 1), 256>>>(
        x, 128, weight, nullptr, bias, s, Tx, 128, 128);

    for (int a = 0; a < 2; a++) {
        const float* Wqkv_a = Wqkv + (size_t)a * 3 * 8 * 16 * 128;  // (384,128)
        const float* Wo_a   = Wo   + (size_t)a * 128 * 128;

        // z = LN1(s)
        ln_kernel<<<(T + 7) / 8, 256>>>(s, ln1_g, ln1_b, z_buf, T);
        // qkv = z @ Wqkv^T   (N = 384)
        gemm_kernel<0, 0><<<dim3(tokBlocks, 3), 256>>>(
            z_buf, 128, Wqkv_a, nullptr, nullptr, big_buf, T, 384, 128);
        // imv = rsa * v  (overwrites z storage; z no longer needed)
        rsa_imv_kernel<<<(T + 7) / 8, 256>>>(big_buf, imv_buf, T);
        // causal cumsum over first 2048 rows per sequence
        cumsum_kernel<<<AA, 128>>>(imv_buf);
        // s += imv @ Wo^T
        gemm_kernel<0, 0><<<dim3(tokBlocks, 1), 256>>>(
            imv_buf, 128, Wo_a, nullptr, s, s, T, 128, 128);
        // z = LN2(s)
        ln_kernel<<<(T + 7) / 8, 256>>>(s, ln2_g, ln2_b, z_buf, T);
        // h = gelu(z @ fc1^T + b1)   (N = 512)
        gemm_kernel<0, 1><<<dim3(tokBlocks, 4), 256>>>(
            z_buf, 128, fc1_w, fc1_b, nullptr, big_buf, T, 512, 128);
        // s = h @ fc2^T + b2 + s     (K = 512)
        gemm_kernel<0, 0><<<dim3(tokBlocks, 1), 256>>>(
            big_buf, 512, fc2_w, fc2_b, s, s, T, 128, 512);
    }
    (void)in_sizes; (void)n_in; (void)out_size;
}

// round 4
// speedup vs baseline: 2.7916x; 2.7916x over previous
#include <cuda_runtime.h>
#include <cuda_bf16.h>
#include <math.h>
#include <stdint.h>

// ---------------------------------------------------------------------------
// EEGformer forward. bf16x3 (hi/lo split) GEMMs via mma.sync m16n8k16 HMMA.
// A=120, B=2048, Bp1=2049, M=128, T = 120*2049 = 245880 tokens.
// ---------------------------------------------------------------------------

#define AA    120
#define BB    2048
#define BP1   2049
#define TTOK  (AA * BP1)      // 245880
#define TXTOK (AA * BB)       // 245760

// Scratch (device globals).
__device__ float g_z  [(size_t)TTOK * 128];   // z planes / imv planes (aliased) ~126MB
__device__ float g_big[(size_t)TTOK * 512];   // x planes / qkv / h planes       ~504MB
__device__ __nv_bfloat16 g_w_hi[278528];
__device__ __nv_bfloat16 g_w_lo[278528];

// ---------------------------------------------------------------------------
// PTX helpers (sm_80-era: ldmatrix / mma.sync / cp.async — valid on sm_100 base)
// ---------------------------------------------------------------------------
__device__ __forceinline__ uint32_t smem_to_u32(const void* p) {
    uint32_t a;
    asm("{ .reg .u64 t; cvta.to.shared.u64 t, %1; cvt.u32.u64 %0, t; }" : "=r"(a) : "l"(p));
    return a;
}
__device__ __forceinline__ void ldm4(uint32_t r[4], uint32_t addr) {
    asm volatile("ldmatrix.sync.aligned.m8n8.x4.shared.b16 {%0,%1,%2,%3}, [%4];"
        : "=r"(r[0]), "=r"(r[1]), "=r"(r[2]), "=r"(r[3]) : "r"(addr));
}
__device__ __forceinline__ void mma16816(float d[4], const uint32_t a[4],
                                         uint32_t b0, uint32_t b1) {
    asm volatile("mma.sync.aligned.m16n8k16.row.col.f32.bf16.bf16.f32 "
        "{%0,%1,%2,%3}, {%4,%5,%6,%7}, {%8,%9}, {%0,%1,%2,%3};"
        : "+f"(d[0]), "+f"(d[1]), "+f"(d[2]), "+f"(d[3])
        : "r"(a[0]), "r"(a[1]), "r"(a[2]), "r"(a[3]), "r"(b0), "r"(b1));
}
__device__ __forceinline__ void cp16(uint32_t saddr, const void* g, bool p) {
    int sz = p ? 16 : 0;
    asm volatile("cp.async.cg.shared.global [%0], [%1], 16, %2;"
        :: "r"(saddr), "l"(g), "r"(sz) : "memory");
}
#define CP_COMMIT() asm volatile("cp.async.commit_group;" ::: "memory")

// ---------------------------------------------------------------------------
// bf16x3 GEMM: out[orow, ncol] = sum_k A[t,k] * W[ncol,k]  (+bias)(gelu)(+addend)
//   A as hi/lo bf16 planes [T][K]; W as hi/lo planes [Nfull][K].
//   Block tile 128(T) x 128(N), BK=32, 8 warps 4x2, warp tile 32x64.
//   grid.y = Nfull/128 (chunk index).
//   Smem per stage (32KB): A_hi(8K) A_lo(8K) B_hi(8K) B_lo(8K), XOR-swizzled:
//     offset(row, kc) = row*64 + ((kc ^ ((row>>1)&3)) << 4), kc = 16B chunk 0..3.
// ---------------------------------------------------------------------------
template<int REMAP, int GELU_F, int OUT_PLANES>
__global__ __launch_bounds__(256, 2)
void mma_gemm(const __nv_bfloat16* __restrict__ a_hi,
              const __nv_bfloat16* __restrict__ a_lo,
              const __nv_bfloat16* __restrict__ w_hi,
              const __nv_bfloat16* __restrict__ w_lo,
              const float* __restrict__ biasv,
              const float* __restrict__ addend,
              float* __restrict__ outf,
              __nv_bfloat16* __restrict__ out_hi,
              __nv_bfloat16* __restrict__ out_lo,
              int T, int K, int Nfull)
{
    extern __shared__ char smem[];
    const uint32_t sbase = smem_to_u32(smem);
    const int tid = threadIdx.x;
    const int wid = tid >> 5, lane = tid & 31;
    const int t0 = blockIdx.x * 128;
    const int nchunk = blockIdx.y;
    const __nv_bfloat16* wch_hi = w_hi + (size_t)nchunk * 128 * K;
    const __nv_bfloat16* wch_lo = w_lo + (size_t)nchunk * 128 * K;

    float acc[2][8][4];
#pragma unroll
    for (int i = 0; i < 2; i++)
#pragma unroll
        for (int j = 0; j < 8; j++)
#pragma unroll
            for (int q = 0; q < 4; q++) acc[i][j][q] = 0.0f;

    const int KT = K >> 5;

    auto stage = [&](int sbuf, int k0) {
        uint32_t sb = sbase + sbuf * 32768;
#pragma unroll
        for (int h = 0; h < 2; h++) {
            int c = tid + h * 256;                    // 0..511
            int row = c >> 2, kc = c & 3;
            uint32_t soff = (uint32_t)row * 64 + ((uint32_t)(kc ^ ((row >> 1) & 3)) << 4);
            int t = t0 + row;
            bool p = t < T;
            size_t ga = (size_t)(p ? t : 0) * K + k0 + kc * 8;
            cp16(sb + 0     + soff, a_hi + ga, p);
            cp16(sb + 8192  + soff, a_lo + ga, p);
            size_t gb = (size_t)row * K + k0 + kc * 8;
            cp16(sb + 16384 + soff, wch_hi + gb, true);
            cp16(sb + 24576 + soff, wch_lo + gb, true);
        }
    };

    stage(0, 0);
    CP_COMMIT();

    for (int kt = 0; kt < KT; kt++) {
        if (kt + 1 < KT) {
            stage((kt + 1) & 1, (kt + 1) << 5);
            CP_COMMIT();
            asm volatile("cp.async.wait_group 1;" ::: "memory");
        } else {
            asm volatile("cp.async.wait_group 0;" ::: "memory");
        }
        __syncthreads();
        uint32_t sb = sbase + (kt & 1) * 32768;

#pragma unroll
        for (int k16 = 0; k16 < 2; k16++) {
            uint32_t ahf[2][4], alf[2][4];
            {
                int r0 = (wid & 3) * 32 + (lane & 15);
                int kc = k16 * 2 + (lane >> 4);
#pragma unroll
                for (int mt = 0; mt < 2; mt++) {
                    int r = r0 + mt * 16;
                    uint32_t off = (uint32_t)r * 64 +
                                   ((uint32_t)(kc ^ ((r >> 1) & 3)) << 4);
                    ldm4(ahf[mt], sb + off);
                    ldm4(alf[mt], sb + 8192 + off);
                }
            }
#pragma unroll
            for (int j = 0; j < 4; j++) {
                int mi = lane >> 3;
                int nr = (wid >> 2) * 64 + j * 16 + (mi >> 1) * 8 + (lane & 7);
                int kc = k16 * 2 + (mi & 1);
                uint32_t off = (uint32_t)nr * 64 +
                               ((uint32_t)(kc ^ ((nr >> 1) & 3)) << 4);
                uint32_t bh[4], bl[4];
                ldm4(bh, sb + 16384 + off);
                ldm4(bl, sb + 24576 + off);
#pragma unroll
                for (int mt = 0; mt < 2; mt++) {
                    mma16816(acc[mt][2 * j],     ahf[mt], bh[0], bh[1]);
                    mma16816(acc[mt][2 * j],     ahf[mt], bl[0], bl[1]);
                    mma16816(acc[mt][2 * j],     alf[mt], bh[0], bh[1]);
                    mma16816(acc[mt][2 * j + 1], ahf[mt], bh[2], bh[3]);
                    mma16816(acc[mt][2 * j + 1], ahf[mt], bl[2], bl[3]);
                    mma16816(acc[mt][2 * j + 1], alf[mt], bh[2], bh[3]);
                }
            }
        }
        __syncthreads();
    }

    // Epilogue: d0/d1 -> row lane>>2, cols (lane&3)*2 + {0,1}; d2/d3 -> row+8.
    const int colbase = nchunk * 128 + (wid >> 2) * 64 + (lane & 3) * 2;
#pragma unroll
    for (int mt = 0; mt < 2; mt++) {
#pragma unroll
        for (int h2 = 0; h2 < 2; h2++) {
            int t = t0 + (wid & 3) * 32 + mt * 16 + (lane >> 2) + h2 * 8;
            if (t >= T) continue;
            size_t orow = REMAP ? ((size_t)t + (size_t)((unsigned)t / 2048u) + 1)
                                : (size_t)t;
#pragma unroll
            for (int nt = 0; nt < 8; nt++) {
                int col = colbase + nt * 8;
                float v0 = acc[mt][nt][h2 * 2 + 0];
                float v1 = acc[mt][nt][h2 * 2 + 1];
                if (biasv) {
                    float2 b2 = *(const float2*)(biasv + col);
                    v0 += b2.x; v1 += b2.y;
                }
                if (GELU_F) {
                    v0 = 0.5f * v0 * (1.0f + erff(v0 * 0.70710678118654752f));
                    v1 = 0.5f * v1 * (1.0f + erff(v1 * 0.70710678118654752f));
                }
                if (addend) {
                    float2 a2 = *(const float2*)(addend + orow * Nfull + col);
                    v0 += a2.x; v1 += a2.y;
                }
                if (OUT_PLANES) {
                    __nv_bfloat162 h = __floats2bfloat162_rn(v0, v1);
                    __nv_bfloat162 l = __floats2bfloat162_rn(
                        v0 - __bfloat162float(h.x), v1 - __bfloat162float(h.y));
                    *(uint32_t*)(out_hi + orow * Nfull + col) = *(uint32_t*)&h;
                    *(uint32_t*)(out_lo + orow * Nfull + col) = *(uint32_t*)&l;
                } else {
                    *(float2*)(outf + orow * Nfull + col) = make_float2(v0, v1);
                }
            }
        }
    }
}

// ---------------------------------------------------------------------------
// fp32 -> bf16 hi/lo split conversion (float4 vectorized).
// ---------------------------------------------------------------------------
__global__ void cvt4_kernel(const float4* __restrict__ src,
                            uint2* __restrict__ hi, uint2* __restrict__ lo, int n4)
{
    int i = blockIdx.x * blockDim.x + threadIdx.x;
    if (i >= n4) return;
    float4 v = src[i];
    __nv_bfloat162 h01 = __floats2bfloat162_rn(v.x, v.y);
    __nv_bfloat162 h23 = __floats2bfloat162_rn(v.z, v.w);
    __nv_bfloat162 l01 = __floats2bfloat162_rn(v.x - __bfloat162float(h01.x),
                                               v.y - __bfloat162float(h01.y));
    __nv_bfloat162 l23 = __floats2bfloat162_rn(v.z - __bfloat162float(h23.x),
                                               v.w - __bfloat162float(h23.y));
    hi[i] = make_uint2(*(uint32_t*)&h01, *(uint32_t*)&h23);
    lo[i] = make_uint2(*(uint32_t*)&l01, *(uint32_t*)&l23);
}

// ---------------------------------------------------------------------------
// LayerNorm over last dim (128) -> bf16 hi/lo planes.
// ---------------------------------------------------------------------------
__global__ void ln_kernel(const float* __restrict__ x,
                          const float* __restrict__ g,
                          const float* __restrict__ b,
                          __nv_bfloat16* __restrict__ z_hi,
                          __nv_bfloat16* __restrict__ z_lo, int T)
{
    int warp = threadIdx.x >> 5;
    int lane = threadIdx.x & 31;
    int t = blockIdx.x * 8 + warp;
    if (t >= T) return;

    float4 v = ((const float4*)(x + (size_t)t * 128))[lane];
    float s = v.x + v.y + v.z + v.w;
#pragma unroll
    for (int o = 16; o >= 1; o >>= 1) s += __shfl_xor_sync(0xffffffffu, s, o);
    float mu = s * (1.0f / 128.0f);
    float dx = v.x - mu, dy = v.y - mu, dz = v.z - mu, dw = v.w - mu;
    float q = dx * dx + dy * dy + dz * dz + dw * dw;
#pragma unroll
    for (int o = 16; o >= 1; o >>= 1) q += __shfl_xor_sync(0xffffffffu, q, o);
    float rs = rsqrtf(q * (1.0f / 128.0f) + 1e-5f);

    float4 gg = ((const float4*)g)[lane];
    float4 bb = ((const float4*)b)[lane];
    float o0 = dx * rs * gg.x + bb.x;
    float o1 = dy * rs * gg.y + bb.y;
    float o2 = dz * rs * gg.z + bb.z;
    float o3 = dw * rs * gg.w + bb.w;

    __nv_bfloat162 h01 = __floats2bfloat162_rn(o0, o1);
    __nv_bfloat162 h23 = __floats2bfloat162_rn(o2, o3);
    __nv_bfloat162 l01 = __floats2bfloat162_rn(o0 - __bfloat162float(h01.x),
                                               o1 - __bfloat162float(h01.y));
    __nv_bfloat162 l23 = __floats2bfloat162_rn(o2 - __bfloat162float(h23.x),
                                               o3 - __bfloat162float(h23.y));
    size_t base = (size_t)t * 128 + lane * 4;
    *(uint2*)(z_hi + base) = make_uint2(*(uint32_t*)&h01, *(uint32_t*)&h23);
    *(uint2*)(z_lo + base) = make_uint2(*(uint32_t*)&l01, *(uint32_t*)&l23);
}

// ---------------------------------------------------------------------------
// rsa/imv: qkv (ld 384, [q|k|v]) -> imv fp32.  head = (n%128)/16.
// ---------------------------------------------------------------------------
__global__ void rsa_imv_kernel(const float* __restrict__ qkv,
                               float* __restrict__ imv, int T)
{
    int warp = threadIdx.x >> 5;
    int lane = threadIdx.x & 31;
    int t = blockIdx.x * 8 + warp;
    if (t >= T) return;
    const float* bp = qkv + (size_t)t * 384;
    float4 q = *(const float4*)(bp + lane * 4);
    float4 k = *(const float4*)(bp + 128 + lane * 4);
    float4 v = *(const float4*)(bp + 256 + lane * 4);
    float p = q.x * k.x + q.y * k.y + q.z * k.z + q.w * k.w;
    p += __shfl_xor_sync(0xffffffffu, p, 1);
    p += __shfl_xor_sync(0xffffffffu, p, 2);
    float rsa = p * 0.25f;   // 1/sqrt(16)
    float4 o = make_float4(rsa * v.x, rsa * v.y, rsa * v.z, rsa * v.w);
    *(float4*)(imv + (size_t)t * 128 + lane * 4) = o;
}

// ---------------------------------------------------------------------------
// cumsum over j in [0,2048) per (i,f); row 2048 converted untouched. Output hi/lo.
// ---------------------------------------------------------------------------
__global__ void cumsum_kernel(const float* __restrict__ imv,
                              __nv_bfloat16* __restrict__ hi,
                              __nv_bfloat16* __restrict__ lo)
{
    int i = blockIdx.x;
    int f = threadIdx.x;
    size_t base = (size_t)i * BP1 * 128 + f;
    float acc = 0.0f;
    for (int j = 0; j < BB; j += 8) {
        float v[8];
#pragma unroll
        for (int u = 0; u < 8; u++) v[u] = imv[base + (size_t)(j + u) * 128];
#pragma unroll
        for (int u = 0; u < 8; u++) {
            acc += v[u];
            __nv_bfloat16 h = __float2bfloat16(acc);
            hi[base + (size_t)(j + u) * 128] = h;
            lo[base + (size_t)(j + u) * 128] = __float2bfloat16(acc - __bfloat162float(h));
        }
    }
    float v = imv[base + (size_t)BB * 128];
    __nv_bfloat16 h = __float2bfloat16(v);
    hi[base + (size_t)BB * 128] = h;
    lo[base + (size_t)BB * 128] = __float2bfloat16(v - __bfloat162float(h));
}

// ---------------------------------------------------------------------------
// cls row: s[i,0,:] = cls[i,:] + bias[i,0,:]
// ---------------------------------------------------------------------------
__global__ void cls_kernel(const float* __restrict__ cls,
                           const float* __restrict__ bias,
                           float* __restrict__ out)
{
    int i = blockIdx.x, l = threadIdx.x;
    out[(size_t)i * BP1 * 128 + l] = cls[i * 128 + l] + bias[(size_t)i * BP1 * 128 + l];
}

// ---------------------------------------------------------------------------
// Launch
// ---------------------------------------------------------------------------
extern "C" void kernel_launch(void* const* d_in, const int* in_sizes, int n_in,
                              void* d_out, int out_size)
{
    const float* x      = (const float*)d_in[0];
    const float* weight = (const float*)d_in[1];
    const float* cls    = (const float*)d_in[2];
    const float* bias   = (const float*)d_in[3];
    const float* Wqkv   = (const float*)d_in[4];
    const float* Wo     = (const float*)d_in[5];
    const float* ln1_g  = (const float*)d_in[6];
    const float* ln1_b  = (const float*)d_in[7];
    const float* ln2_g  = (const float*)d_in[8];
    const float* ln2_b  = (const float*)d_in[9];
    const float* fc1_w  = (const float*)d_in[10];
    const float* fc1_b  = (const float*)d_in[11];
    const float* fc2_w  = (const float*)d_in[12];
    const float* fc2_b  = (const float*)d_in[13];
    float* s = (float*)d_out;

    void *pz, *pbig, *pwh, *pwl;
    cudaGetSymbolAddress(&pz,   g_z);
    cudaGetSymbolAddress(&pbig, g_big);
    cudaGetSymbolAddress(&pwh,  g_w_hi);
    cudaGetSymbolAddress(&pwl,  g_w_lo);
    char* zb  = (char*)pz;
    char* big = (char*)pbig;
    __nv_bfloat16* w_hi = (__nv_bfloat16*)pwh;
    __nv_bfloat16* w_lo = (__nv_bfloat16*)pwl;

    const int T  = TTOK;
    const int Tx = TXTOK;
    const int tokBlocks = (T + 127) / 128;   // 1922
    const int txBlocks  = Tx / 128;          // 1920

    // scratch layouts
    __nv_bfloat16* z_hi   = (__nv_bfloat16*)zb;                 // T*128
    __nv_bfloat16* z_lo   = z_hi + (size_t)T * 128;
    __nv_bfloat16* imv_hi = z_hi;                               // alias (z dead)
    __nv_bfloat16* imv_lo = z_lo;
    float*         qkv    = (float*)big;                        // T*384
    float*         imv32  = qkv + (size_t)T * 384;              // T*128
    __nv_bfloat16* h_hi   = (__nv_bfloat16*)big;                // T*512
    __nv_bfloat16* h_lo   = h_hi + (size_t)T * 512;
    __nv_bfloat16* x_hi   = (__nv_bfloat16*)big;                // Tx*128
    __nv_bfloat16* x_lo   = x_hi + (size_t)Tx * 128;

    // weight plane offsets (elements)
    const int OFF_W    = 0;
    const int OFF_QKV  = 16384;
    const int OFF_WO   = 114688;
    const int OFF_FC1  = 147456;
    const int OFF_FC2  = 212992;

    const int SMEM_SZ = 65536;
    cudaFuncSetAttribute(mma_gemm<1,0,0>, cudaFuncAttributeMaxDynamicSharedMemorySize, SMEM_SZ);
    cudaFuncSetAttribute(mma_gemm<0,0,0>, cudaFuncAttributeMaxDynamicSharedMemorySize, SMEM_SZ);
    cudaFuncSetAttribute(mma_gemm<0,1,1>, cudaFuncAttributeMaxDynamicSharedMemorySize, SMEM_SZ);

    // --- weight + x conversions ---
    cvt4_kernel<<<(16384/4 + 255)/256, 256>>>((const float4*)weight,
        (uint2*)(w_hi + OFF_W), (uint2*)(w_lo + OFF_W), 16384/4);
    cvt4_kernel<<<(98304/4 + 255)/256, 256>>>((const float4*)Wqkv,
        (uint2*)(w_hi + OFF_QKV), (uint2*)(w_lo + OFF_QKV), 98304/4);
    cvt4_kernel<<<(32768/4 + 255)/256, 256>>>((const float4*)Wo,
        (uint2*)(w_hi + OFF_WO), (uint2*)(w_lo + OFF_WO), 32768/4);
    cvt4_kernel<<<(65536/4 + 255)/256, 256>>>((const float4*)fc1_w,
        (uint2*)(w_hi + OFF_FC1), (uint2*)(w_lo + OFF_FC1), 65536/4);
    cvt4_kernel<<<(65536/4 + 255)/256, 256>>>((const float4*)fc2_w,
        (uint2*)(w_hi + OFF_FC2), (uint2*)(w_lo + OFF_FC2), 65536/4);
    {
        int n4 = Tx * 128 / 4;
        cvt4_kernel<<<(n4 + 255)/256, 256>>>((const float4*)x, (uint2*)x_hi, (uint2*)x_lo, n4);
    }

    // s = concat([cls, x @ W^T], 1) + bias
    cls_kernel<<<AA, 128>>>(cls, bias, s);
    mma_gemm<1,0,0><<<dim3(txBlocks, 1), 256, SMEM_SZ>>>(
        x_hi, x_lo, w_hi + OFF_W, w_lo + OFF_W, nullptr, bias, s,
        nullptr, nullptr, Tx, 128, 128);

    for (int a = 0; a < 2; a++) {
        const __nv_bfloat16* wq_hi = w_hi + OFF_QKV + a * 49152;
        const __nv_bfloat16* wq_lo = w_lo + OFF_QKV + a * 49152;
        const __nv_bfloat16* wo_hi = w_hi + OFF_WO + a * 16384;
        const __nv_bfloat16* wo_lo = w_lo + OFF_WO + a * 16384;

        // z = LN1(s)
        ln_kernel<<<(T + 7) / 8, 256>>>(s, ln1_g, ln1_b, z_hi, z_lo, T);
        // qkv = z @ Wqkv^T (N=384)
        mma_gemm<0,0,0><<<dim3(tokBlocks, 3), 256, SMEM_SZ>>>(
            z_hi, z_lo, wq_hi, wq_lo, nullptr, nullptr, qkv,
            nullptr, nullptr, T, 128, 384);
        // imv = rsa * v (overwrites z storage)
        rsa_imv_kernel<<<(T + 7) / 8, 256>>>(qkv, imv32, T);
        cumsum_kernel<<<AA, 128>>>(imv32, imv_hi, imv_lo);
        // s += imv @ Wo^T
        mma_gemm<0,0,0><<<dim3(tokBlocks, 1), 256, SMEM_SZ>>>(
            imv_hi, imv_lo, wo_hi, wo_lo, nullptr, s, s,
            nullptr, nullptr, T, 128, 128);
        // z = LN2(s)
        ln_kernel<<<(T + 7) / 8, 256>>>(s, ln2_g, ln2_b, z_hi, z_lo, T);
        // h = gelu(z @ fc1^T + b1) (N=512) -> planes
        mma_gemm<0,1,1><<<dim3(tokBlocks, 4), 256, SMEM_SZ>>>(
            z_hi, z_lo, w_hi + OFF_FC1, w_lo + OFF_FC1, fc1_b, nullptr,
            nullptr, h_hi, h_lo, T, 128, 512);
        // s = h @ fc2^T + b2 + s  (K=512)
        mma_gemm<0,0,0><<<dim3(tokBlocks, 1), 256, SMEM_SZ>>>(
            h_hi, h_lo, w_hi + OFF_FC2, w_lo + OFF_FC2, fc2_b, s, s,
            nullptr, nullptr, T, 512, 128);
    }
    (void)in_sizes; (void)n_in; (void)out_size;
}